// round 17
// baseline (speedup 1.0000x reference)
#include <cuda_runtime.h>
#include <cuda_fp16.h>
#include <cstdint>

#define BATCH  256
#define SEQ    100
#define CH     512
#define QP     1024
#define MTOT   (BATCH*SEQ)
#define MPAD   (MTOT+28)
#define DIMIN  2048
#define LAYERS 6
typedef __half hf;

// ---------------- scratch (zero-initialized device globals) ----------------
__device__ float g_X [MPAD*CH];
__device__ hf    g_Xh[MPAD*CH];
__device__ hf    g_Ih[MTOT*DIMIN];
__device__ hf    g_QKVh[MPAD*QP];
__device__ hf    g_TRh[CH*DIMIN];
__device__ hf    g_GWh[LAYERS*CH*CH];
__device__ hf    g_TWh[LAYERS*CH*CH];
__device__ hf    g_PWTh[LAYERS*CH*CH];
__device__ hf    g_WWh[LAYERS*CH*CH];
__device__ hf    g_Vh[LAYERS*CH*CH];
__device__ hf    g_Mh[LAYERS*CH*CH];
__device__ hf    g_R[BATCH*128*128];
__device__ float g_S[BATCH*128];
__device__ float g_wgb[LAYERS*CH], g_u[LAYERS*CH], g_v[LAYERS*CH], g_cc[LAYERS];

// ---------------- helpers ----------------
__device__ __forceinline__ uint32_t smem_u32(const void* p){
    uint32_t a;
    asm("{ .reg .u64 t; cvta.to.shared.u64 t, %1; cvt.u32.u64 %0, t; }" : "=r"(a) : "l"(p));
    return a;
}
__device__ __forceinline__ void ldsm4(uint32_t &r0, uint32_t &r1, uint32_t &r2, uint32_t &r3, uint32_t a){
    asm volatile("ldmatrix.sync.aligned.m8n8.x4.shared.b16 {%0,%1,%2,%3}, [%4];"
        : "=r"(r0), "=r"(r1), "=r"(r2), "=r"(r3) : "r"(a));
}
__device__ __forceinline__ void ldsm4t(uint32_t &r0, uint32_t &r1, uint32_t &r2, uint32_t &r3, uint32_t a){
    asm volatile("ldmatrix.sync.aligned.m8n8.x4.trans.shared.b16 {%0,%1,%2,%3}, [%4];"
        : "=r"(r0), "=r"(r1), "=r"(r2), "=r"(r3) : "r"(a));
}
__device__ __forceinline__ void mma16816(float* c, const uint32_t* a, const uint32_t* b){
    asm volatile("mma.sync.aligned.m16n8k16.row.col.f32.f16.f16.f32 "
        "{%0,%1,%2,%3}, {%4,%5,%6,%7}, {%8,%9}, {%0,%1,%2,%3};"
        : "+f"(c[0]), "+f"(c[1]), "+f"(c[2]), "+f"(c[3])
        : "r"(a[0]), "r"(a[1]), "r"(a[2]), "r"(a[3]), "r"(b[0]), "r"(b[1]));
}
#define CP16(dst, src) asm volatile("cp.async.cg.shared.global [%0], [%1], 16;" :: "r"(dst), "l"(src))
#define CPCOMMIT()     asm volatile("cp.async.commit_group;" ::: "memory")
#define CPWAIT(n)      asm volatile("cp.async.wait_group %0;" :: "n"(n) : "memory")

__device__ __forceinline__ void st_h2(hf* p, hf a, hf b){
    *(__half2*)p = __halves2half2(a, b);
}

#define STAGES 3
#define STG_B  32768
#define SMEM_DYN (STAGES*STG_B)
#define SMEM_Y  65536

#define DECL_ACC() \
    float acc[2][8][4]; \
    _Pragma("unroll") \
    for (int i = 0; i < 2; i++) \
        _Pragma("unroll") \
        for (int j = 0; j < 8; j++) \
            _Pragma("unroll") \
            for (int qq = 0; qq < 4; qq++) acc[i][j][qq] = 0.f;

// TN single-pass stage: A hi (128r x 64k, 16KB) + B hi (128r x 64k, 16KB)
#define TN1_STAGE_LOAD(base, Ahp, Bhp, pitchA, pitchB, k0) \
    { \
        _Pragma("unroll") \
        for (int i = 0; i < 8; i++){ \
            int chunk = tid + i * 256; \
            if (chunk < 1024){ \
                int row = chunk >> 3, ch = chunk & 7; \
                const hf* src = (Ahp) + (size_t)row * (pitchA) + (k0) + ch * 8; \
                uint32_t dst = (base) + row * 128 + ((ch ^ (row & 7)) << 4); \
                CP16(dst, src); \
            } else { \
                int cid = chunk - 1024; \
                int row = cid >> 3, ch = cid & 7; \
                const hf* src = (Bhp) + (size_t)row * (pitchB) + (k0) + ch * 8; \
                uint32_t dst = (base) + 16384 + row * 128 + ((ch ^ (row & 7)) << 4); \
                CP16(dst, src); \
            } \
        } \
    }

// TN single-pass mainloop (pipelined)
#define TN1_MAINLOOP_BODY(sA, sB) \
    { \
        uint32_t ahf[4][2][4]; \
        _Pragma("unroll") \
        for (int kt = 0; kt < 4; kt++){ \
            _Pragma("unroll") \
            for (int mt = 0; mt < 2; mt++){ \
                int row = wm*32 + mt*16 + (g & 1)*8 + r; \
                int sw = row & 7; \
                int ch = kt*2 + (g >> 1); \
                ldsm4(ahf[kt][mt][0], ahf[kt][mt][1], ahf[kt][mt][2], ahf[kt][mt][3], \
                      (sA) + row*128 + ((ch ^ sw) << 4)); \
            } \
        } \
        _Pragma("unroll") \
        for (int kt = 0; kt < 4; kt++){ \
            uint32_t bb[2][4]; \
            { \
                int row = wn*64 + (g & 1)*8 + r; \
                int sw = row & 7; \
                int ch = kt*2 + (g >> 1); \
                ldsm4(bb[0][0], bb[0][1], bb[0][2], bb[0][3], \
                      (sB) + row*128 + ((ch ^ sw) << 4)); \
            } \
            _Pragma("unroll") \
            for (int np = 0; np < 4; np++){ \
                if (np + 1 < 4){ \
                    int row = wn*64 + (np+1)*16 + (g & 1)*8 + r; \
                    int sw = row & 7; \
                    int ch = kt*2 + (g >> 1); \
                    ldsm4(bb[(np+1)&1][0], bb[(np+1)&1][1], bb[(np+1)&1][2], bb[(np+1)&1][3], \
                          (sB) + row*128 + ((ch ^ sw) << 4)); \
                } \
                uint32_t b0[2] = {bb[np&1][0], bb[np&1][2]}; \
                uint32_t b1[2] = {bb[np&1][1], bb[np&1][3]}; \
                _Pragma("unroll") \
                for (int mt = 0; mt < 2; mt++){ \
                    mma16816(acc[mt][2*np],   ahf[kt][mt], b0); \
                    mma16816(acc[mt][2*np+1], ahf[kt][mt], b1); \
                } \
            } \
        } \
    }

// NN single-pass stage
#define NN1_STAGE_LOAD(base, Ahp, Bhp, pitchA, pitchB, k0, n0v) \
    { \
        _Pragma("unroll") \
        for (int i = 0; i < 8; i++){ \
            int chunk = tid + i * 256; \
            if (chunk < 1024){ \
                int row = chunk >> 3, ch = chunk & 7; \
                const hf* src = (Ahp) + (size_t)row * (pitchA) + (k0) + ch * 8; \
                uint32_t dst = (base) + row * 128 + ((ch ^ (row & 7)) << 4); \
                CP16(dst, src); \
            } else { \
                int cid = chunk - 1024; \
                int k = cid >> 4, cn = cid & 15; \
                const hf* src = (Bhp) + (size_t)((k0) + k) * (pitchB) + (n0v) + cn * 8; \
                uint32_t dst = (base) + 16384 + k * 256 + ((cn ^ (k & 7)) << 4); \
                CP16(dst, src); \
            } \
        } \
    }

// NN single-pass mainloop (pipelined)
#define NN1_MAINLOOP_BODY(sA, sG) \
    { \
        uint32_t ahf[4][2][4]; \
        _Pragma("unroll") \
        for (int kt = 0; kt < 4; kt++){ \
            _Pragma("unroll") \
            for (int mt = 0; mt < 2; mt++){ \
                int row = wm*32 + mt*16 + (g & 1)*8 + r; \
                int sw = row & 7; \
                int ch = kt*2 + (g >> 1); \
                ldsm4(ahf[kt][mt][0], ahf[kt][mt][1], ahf[kt][mt][2], ahf[kt][mt][3], \
                      (sA) + row*128 + ((ch ^ sw) << 4)); \
            } \
        } \
        _Pragma("unroll") \
        for (int kt = 0; kt < 4; kt++){ \
            int krow = kt*16 + (lane & 7) + (m & 1)*8; \
            int ksw = krow & 7; \
            uint32_t bb[2][4]; \
            { \
                int cb = wn*8 + (m >> 1); \
                ldsm4t(bb[0][0], bb[0][1], bb[0][2], bb[0][3], \
                       (sG) + krow*256 + ((cb ^ ksw) << 4)); \
            } \
            _Pragma("unroll") \
            for (int np = 0; np < 4; np++){ \
                if (np + 1 < 4){ \
                    int cb = wn*8 + (np+1)*2 + (m >> 1); \
                    ldsm4t(bb[(np+1)&1][0], bb[(np+1)&1][1], bb[(np+1)&1][2], bb[(np+1)&1][3], \
                           (sG) + krow*256 + ((cb ^ ksw) << 4)); \
                } \
                uint32_t b0[2] = {bb[np&1][0], bb[np&1][1]}; \
                uint32_t b1[2] = {bb[np&1][2], bb[np&1][3]}; \
                _Pragma("unroll") \
                for (int mt = 0; mt < 2; mt++){ \
                    mma16816(acc[mt][2*np],   ahf[kt][mt], b0); \
                    mma16816(acc[mt][2*np+1], ahf[kt][mt], b1); \
                } \
            } \
        } \
    }

// ---------------- combined enc + vm GEMM launch -----------------------------
__global__ __launch_bounds__(256, 2)
void encvm_gemm(const float* __restrict__ bias)
{
    extern __shared__ __align__(1024) char smem[];
    uint32_t sb = smem_u32(smem);
    int tid = threadIdx.x, wid = tid >> 5, lane = tid & 31;
    int bid = blockIdx.x;
    int wm = wid >> 1, wn = wid & 1;
    int g = lane >> 3, r = lane & 7;

    if (bid < 192){
        int z = bid >> 4, by = (bid >> 2) & 3, bx = bid & 3;
        int n0 = bx * 128, m0 = by * 128;
        int l = (z < LAYERS) ? z : z - LAYERS;
        const hf *Ah, *Bh;
        hf *Oh;
        if (z < LAYERS){
            Ah = g_WWh + (size_t)l*CH*CH + (size_t)m0*CH;
            Bh = g_GWh + (size_t)l*CH*CH;
            Oh = g_Vh  + (size_t)l*CH*CH;
        } else {
            Ah = g_PWTh + (size_t)l*CH*CH + (size_t)m0*CH;
            Bh = g_TWh  + (size_t)l*CH*CH;
            Oh = g_Mh   + (size_t)l*CH*CH;
        }
        DECL_ACC();
        int m = lane >> 3;

        const int kiters = CH / 64;
        #pragma unroll
        for (int s = 0; s < STAGES - 1; s++){
            NN1_STAGE_LOAD(sb + s*STG_B, Ah, Bh, CH, CH, s*64, n0);
            CPCOMMIT();
        }
        for (int it = 0; it < kiters; it++){
            CPWAIT(STAGES - 2);
            __syncthreads();
            uint32_t sA = sb + (it % STAGES) * STG_B;
            NN1_MAINLOOP_BODY(sA, sA + 16384);
            if (it + STAGES - 1 < kiters){
                int s2 = (it + STAGES - 1) % STAGES;
                NN1_STAGE_LOAD(sb + s2*STG_B, Ah, Bh, CH, CH, (it + STAGES - 1)*64, n0);
            }
            CPCOMMIT();
        }
        CPWAIT(0);

        int q = lane >> 2, p = lane & 3;
        #pragma unroll
        for (int mt = 0; mt < 2; mt++)
            #pragma unroll
            for (int nt = 0; nt < 8; nt++){
                int c = wn*64 + nt*8 + 2*p;
                #pragma unroll
                for (int h = 0; h < 2; h++){
                    int row = m0 + wm*32 + mt*16 + q + h*8;
                    st_h2(Oh + (size_t)row * CH + n0 + c,
                          __float2half_rn(acc[mt][nt][2*h+0]),
                          __float2half_rn(acc[mt][nt][2*h+1]));
                }
            }
    } else {
        int e = bid - 192;
        int n0 = (e & 3) * 128, m0 = (e >> 2) * 128;
        const int K = DIMIN;
        const hf* Ah = g_Ih + (size_t)m0 * K;
        const hf* Bh = g_TRh + (size_t)n0 * K;
        DECL_ACC();

        const int kiters = K / 64;
        #pragma unroll
        for (int s = 0; s < STAGES - 1; s++){
            TN1_STAGE_LOAD(sb + s*STG_B, Ah, Bh, K, K, s*64);
            CPCOMMIT();
        }
        for (int it = 0; it < kiters; it++){
            CPWAIT(STAGES - 2);
            __syncthreads();
            uint32_t sA = sb + (it % STAGES) * STG_B;
            TN1_MAINLOOP_BODY(sA, sA + 16384);
            if (it + STAGES - 1 < kiters){
                int s2 = (it + STAGES - 1) % STAGES;
                TN1_STAGE_LOAD(sb + s2*STG_B, Ah, Bh, K, K, (it + STAGES - 1)*64);
            }
            CPCOMMIT();
        }
        CPWAIT(0);
        __syncthreads();
        float* cf = (float*)smem;
        if (tid < 128) cf[tid] = bias[n0 + tid];
        __syncthreads();

        int q = lane >> 2, p = lane & 3;
        #pragma unroll
        for (int mt = 0; mt < 2; mt++)
            #pragma unroll
            for (int nt = 0; nt < 8; nt++){
                int c = wn*64 + nt*8 + 2*p;
                #pragma unroll
                for (int h = 0; h < 2; h++){
                    int row = m0 + wm*32 + mt*16 + q + h*8;
                    float v0 = acc[mt][nt][2*h+0] + cf[c];
                    float v1 = acc[mt][nt][2*h+1] + cf[c+1];
                    size_t off = (size_t)row * CH + n0 + c;
                    *(float2*)(g_X + off) = make_float2(v0, v1);
                    st_h2(g_Xh + off, __float2half_rn(v0), __float2half_rn(v1));
                }
            }
    }
}

// ---------------- QKV GEMM (TN single-pass, KC=64; B = [V | M]) ------------
__global__ __launch_bounds__(256, 2)
void qkv_gemm(int l)
{
    extern __shared__ __align__(1024) char smem[];
    uint32_t sb = smem_u32(smem);
    int tid = threadIdx.x, wid = tid >> 5, lane = tid & 31;
    int n0 = blockIdx.x * 128, m0 = blockIdx.y * 128;
    const int K = CH;
    const hf* Ah = g_Xh + (size_t)m0 * K;
    const hf* Bh = (n0 < 512)
        ? g_Vh + (size_t)l*CH*CH + (size_t)n0 * K
        : g_Mh + (size_t)l*CH*CH + (size_t)(n0-512) * K;
    DECL_ACC();

    const int kiters = K / 64;
    #pragma unroll
    for (int s = 0; s < STAGES - 1; s++){
        TN1_STAGE_LOAD(sb + s*STG_B, Ah, Bh, K, K, s*64);
        CPCOMMIT();
    }

    int wm = wid >> 1, wn = wid & 1;
    int g = lane >> 3, r = lane & 7;

    for (int it = 0; it < kiters; it++){
        CPWAIT(STAGES - 2);
        __syncthreads();
        uint32_t sA = sb + (it % STAGES) * STG_B;
        TN1_MAINLOOP_BODY(sA, sA + 16384);
        if (it + STAGES - 1 < kiters){
            int s2 = (it + STAGES - 1) % STAGES;
            TN1_STAGE_LOAD(sb + s2*STG_B, Ah, Bh, K, K, (it + STAGES - 1)*64);
        }
        CPCOMMIT();
    }
    CPWAIT(0);

    int q = lane >> 2, p = lane & 3;
    #pragma unroll
    for (int mt = 0; mt < 2; mt++)
        #pragma unroll
        for (int nt = 0; nt < 8; nt++){
            int c = wn*64 + nt*8 + 2*p;
            #pragma unroll
            for (int h = 0; h < 2; h++){
                int row = m0 + wm*32 + mt*16 + q + h*8;
                size_t off = (size_t)row * QP + n0 + c;
                st_h2(g_QKVh + off,
                      __float2half_rn(acc[mt][nt][2*h+0]),
                      __float2half_rn(acc[mt][nt][2*h+1]));
            }
        }
}

// ---------------- attn_r: R = (Z·Xb^T + corrections)/SEQ -> g_R, s -> g_S --
__global__ __launch_bounds__(256, 2)
void attn_r(int l)
{
    extern __shared__ __align__(1024) char smem[];
    __shared__ float s_sum[128], s_p[128], s_q[128];
    __shared__ float s_u[512], s_v[512];
    uint32_t sb = smem_u32(smem);
    int tid = threadIdx.x, wid = tid >> 5, lane = tid & 31;
    int b = blockIdx.x;
    const hf* Zh  = g_QKVh + (size_t)b*SEQ*QP + 512;
    const hf* Xbh = g_Xh + (size_t)b*SEQ*CH;
    DECL_ACC();

    #pragma unroll
    for (int z = 0; z < 2; z++){
        int c = tid + z*256;
        s_u[c] = g_u[l*CH + c];
        s_v[c] = g_v[l*CH + c];
    }
    if (tid < 128){ s_sum[tid] = 0.f; s_p[tid] = 0.f; s_q[tid] = 0.f; }

    const int kit1 = CH / 64;
    #pragma unroll
    for (int s = 0; s < 2; s++){
        TN1_STAGE_LOAD(sb + s*STG_B, Zh, Xbh, QP, CH, s*64);
        CPCOMMIT();
    }
    __syncthreads();

    for (int row = wid; row < SEQ; row += 8){
        const hf* xr = g_Xh + (size_t)(b*SEQ + row)*CH + lane*8;
        float pa = 0.f, qa = 0.f;
        #pragma unroll
        for (int z = 0; z < 2; z++){
            uint4 xv = *(const uint4*)(xr + z*256);
            const hf* xh = (const hf*)&xv;
            #pragma unroll
            for (int j = 0; j < 8; j++){
                float xf = __half2float(xh[j]);
                int idx = lane*8 + z*256 + j;
                pa += xf * s_u[idx];
                qa += xf * s_v[idx];
            }
        }
        #pragma unroll
        for (int o = 16; o > 0; o >>= 1){
            pa += __shfl_down_sync(0xFFFFFFFFu, pa, o);
            qa += __shfl_down_sync(0xFFFFFFFFu, qa, o);
        }
        if (lane == 0){ s_p[row] = pa; s_q[row] = qa; }
    }

    int wm = wid >> 1, wn = wid & 1;
    int g = lane >> 3, r = lane & 7;

    for (int it = 0; it < kit1; it++){
        CPWAIT(1);
        __syncthreads();
        uint32_t sA = sb + (it % 3) * STG_B;
        TN1_MAINLOOP_BODY(sA, sA + 16384);
        if (it + 2 < kit1){
            int s2 = (it + 2) % 3;
            TN1_STAGE_LOAD(sb + s2*STG_B, Zh, Xbh, QP, CH, (it + 2)*64);
        }
        CPCOMMIT();
    }
    CPWAIT(0);
    __syncthreads();   // s_p/s_q complete

    const float inv_n = 1.0f / (float)SEQ;
    const float cl = g_cc[l];
    int q = lane >> 2, p = lane & 3;
    hf* Rb = g_R + (size_t)b * 16384;
    float rs[2][2] = {{0.f, 0.f}, {0.f, 0.f}};
    #pragma unroll
    for (int mt = 0; mt < 2; mt++)
        #pragma unroll
        for (int nt = 0; nt < 8; nt++){
            int c = wn*64 + nt*8 + 2*p;
            #pragma unroll
            for (int h = 0; h < 2; h++){
                int row = wm*32 + mt*16 + q + h*8;
                bool okr = row < SEQ;
                float v0 = (okr && c   < SEQ)
                    ? (acc[mt][nt][2*h+0] + s_p[row] + s_q[c]   + cl) * inv_n : 0.f;
                float v1 = (okr && c+1 < SEQ)
                    ? (acc[mt][nt][2*h+1] + s_p[row] + s_q[c+1] + cl) * inv_n : 0.f;
                rs[mt][h] += v0 + v1;
                st_h2(Rb + row*128 + c, __float2half_rn(v0), __float2half_rn(v1));
            }
        }
    #pragma unroll
    for (int mt = 0; mt < 2; mt++)
        #pragma unroll
        for (int h = 0; h < 2; h++)
            atomicAdd(&s_sum[wm*32 + mt*16 + q + h*8], rs[mt][h]);
    __syncthreads();
    if (tid < 128) g_S[b*128 + tid] = s_sum[tid];
}

// ---------------- attn_y: Y n-tile = R·G + s·wgb, BN, +resid ---------------
// grid (4, BATCH): one 128x128 y-tile per CTA; R + G resident in smem.
template<int LAST>
__global__ __launch_bounds__(256, 2)
void attn_y(float* outp, int l,
            const float* __restrict__ wb,
            const float* __restrict__ gamma, const float* __restrict__ beta,
            const float* __restrict__ mean,  const float* __restrict__ var)
{
    extern __shared__ __align__(1024) char smem[];
    __shared__ float s_cs[128], s_cf[128], s_cw[128];
    uint32_t sb = smem_u32(smem);
    int tid = threadIdx.x, wid = tid >> 5, lane = tid & 31;
    int nt0 = blockIdx.x, b = blockIdx.y;
    int n0 = nt0 * 128;

    // load R (32KB) and G (32KB) into smem, swizzled
    const hf* Rb = g_R + (size_t)b * 16384;
    #pragma unroll
    for (int i = 0; i < 8; i++){
        int chunk = tid + i * 256;
        int row = chunk >> 4, cn = chunk & 15;
        CP16(sb + row*256 + ((cn ^ (row & 7)) << 4), Rb + row*128 + cn*8);
    }
    #pragma unroll
    for (int i = 0; i < 8; i++){
        int chunk = tid + i * 256;
        int k = chunk >> 4, cn = chunk & 15;
        const hf* src = g_QKVh + (size_t)(b*SEQ + k) * QP + n0 + cn*8;
        CP16(sb + 32768 + k*256 + ((cn ^ (k & 7)) << 4), src);
    }
    CPCOMMIT();

    if (tid < 128){
        int c = n0 + tid;
        float iv = gamma[c] * rsqrtf(var[c] + 1e-5f);
        s_cs[tid] = iv;
        s_cf[tid] = (wb[c] - mean[c]) * iv + beta[c];
        s_cw[tid] = g_wgb[l*CH + c];
    }
    DECL_ACC();

    int wm = wid >> 1, wn = wid & 1;
    int g = lane >> 3, r = lane & 7;
    int m = lane >> 3;
    int q = lane >> 2, p = lane & 3;

    float sv[2][2];
    #pragma unroll
    for (int mt = 0; mt < 2; mt++)
        #pragma unroll
        for (int h = 0; h < 2; h++)
            sv[mt][h] = g_S[b*128 + wm*32 + mt*16 + q + h*8];

    CPWAIT(0);
    __syncthreads();

    uint32_t sG = sb + 32768;
    #pragma unroll
    for (int it = 0; it < 4; it++){
        #pragma unroll
        for (int kt = 0; kt < 2; kt++){
            uint32_t ah[2][4];
            #pragma unroll
            for (int mt = 0; mt < 2; mt++){
                int row = wm*32 + mt*16 + (g & 1)*8 + r;
                int sw = row & 7;
                int ch = it*4 + kt*2 + (g >> 1);
                ldsm4(ah[mt][0], ah[mt][1], ah[mt][2], ah[mt][3],
                      sb + row*256 + ((ch ^ sw) << 4));
            }
            int krow = it*32 + kt*16 + (lane & 7) + (m & 1)*8;
            int ksw = krow & 7;
            uint32_t bb[2][4];
            {
                int cb = wn*8 + (m >> 1);
                ldsm4t(bb[0][0], bb[0][1], bb[0][2], bb[0][3],
                       sG + krow*256 + ((cb ^ ksw) << 4));
            }
            #pragma unroll
            for (int np = 0; np < 4; np++){
                if (np + 1 < 4){
                    int cb = wn*8 + (np+1)*2 + (m >> 1);
                    ldsm4t(bb[(np+1)&1][0], bb[(np+1)&1][1], bb[(np+1)&1][2], bb[(np+1)&1][3],
                           sG + krow*256 + ((cb ^ ksw) << 4));
                }
                uint32_t b0[2] = {bb[np&1][0], bb[np&1][1]};
                uint32_t b1[2] = {bb[np&1][2], bb[np&1][3]};
                #pragma unroll
                for (int mt = 0; mt < 2; mt++){
                    mma16816(acc[mt][2*np],   ah[mt], b0);
                    mma16816(acc[mt][2*np+1], ah[mt], b1);
                }
            }
        }
    }

    #pragma unroll
    for (int mt = 0; mt < 2; mt++)
        #pragma unroll
        for (int nt = 0; nt < 8; nt++){
            int c = wn*64 + nt*8 + 2*p;
            int gc = n0 + c;
            #pragma unroll
            for (int h = 0; h < 2; h++){
                int row = wm*32 + mt*16 + q + h*8;
                if (row < SEQ){
                    size_t off = (size_t)(b*SEQ + row) * CH + gc;
                    float2 rv = *(const float2*)(g_X + off);
                    float v0 = (acc[mt][nt][2*h+0] + sv[mt][h]*s_cw[c])
                                 * s_cs[c]   + s_cf[c]   + rv.x;
                    float v1 = (acc[mt][nt][2*h+1] + sv[mt][h]*s_cw[c+1])
                                 * s_cs[c+1] + s_cf[c+1] + rv.y;
                    *(float2*)(outp + off) = make_float2(v0, v1);
                    if (!LAST)
                        st_h2(g_Xh + off, __float2half_rn(v0), __float2half_rn(v1));
                }
            }
        }
}

// ---------------- unified prep launch ----------------
#define N4_IMG ((long)MTOT*DIMIN/4)
#define N4_TR  ((long)CH*DIMIN/4)
#define N4_L   ((long)LAYERS*CH*CH/4)
#define N4_TOT (N4_IMG + N4_TR + 3*N4_L)
#define SPLIT_CTAS ((unsigned)((N4_TOT + 255)/256))
#define TSP_CTAS   (256u*LAYERS)
#define PREP_CTAS  ((unsigned)((3*LAYERS*CH + LAYERS + 255)/256))

__global__ void prep_all(const float* __restrict__ img, const float* __restrict__ trans_w,
                         const float* __restrict__ gw, const float* __restrict__ tw,
                         const float* __restrict__ ww, const float* __restrict__ pw,
                         const float* __restrict__ gb, const float* __restrict__ pb,
                         const float* __restrict__ tb)
{
    __shared__ float tbuf[32][33];
    unsigned bid = blockIdx.x;
    int tid = threadIdx.x;

    if (bid < SPLIT_CTAS){
        long t = (long)bid * 256 + tid;
        if (t >= N4_TOT) return;
        const float* src; hf* dh;
        if (t < N4_IMG){ src = img; dh = g_Ih; }
        else if ((t -= N4_IMG) < N4_TR){ src = trans_w; dh = g_TRh; }
        else if ((t -= N4_TR) < N4_L){ src = gw; dh = g_GWh; }
        else if ((t -= N4_L) < N4_L){ src = tw; dh = g_TWh; }
        else { t -= N4_L; src = ww; dh = g_WWh; }
        float4 x = ((const float4*)src)[t];
        long d = t * 4;
        st_h2(dh + d,     __float2half_rn(x.x), __float2half_rn(x.y));
        st_h2(dh + d + 2, __float2half_rn(x.z), __float2half_rn(x.w));
    } else if (bid < SPLIT_CTAS + TSP_CTAS){
        unsigned b2 = bid - SPLIT_CTAS;
        int l = b2 >> 8;
        int rem = b2 & 255;
        int d0 = (rem & 15) * 32, c0 = (rem >> 4) * 32;
        int tx = tid & 31, ty = tid >> 5;
        const float* src = pw + (size_t)l*CH*CH;
        #pragma unroll
        for (int k = 0; k < 4; k++)
            tbuf[ty + 8*k][tx] = src[(size_t)(c0 + ty + 8*k)*CH + d0 + tx];
        __syncthreads();
        hf* dh = g_PWTh + (size_t)l*CH*CH;
        #pragma unroll
        for (int k = 0; k < 4; k++)
            dh[(size_t)(d0 + ty + 8*k)*CH + c0 + tx] = __float2half_rn(tbuf[tx][ty + 8*k]);
    } else {
        const int LC = LAYERS*CH;
        int i = (int)(bid - SPLIT_CTAS - TSP_CTAS) * 256 + tid;
        if (i < LC){
            int l = i / CH, o = i % CH;
            const float4* w = (const float4*)(ww + (size_t)l*CH*CH + (size_t)o*CH);
            const float4* bs = (const float4*)(gb + l*CH);
            float s = 0.f;
            for (int k = 0; k < CH/4; k++){
                float4 a = w[k], c4 = bs[k];
                s += a.x*c4.x + a.y*c4.y + a.z*c4.z + a.w*c4.w;
            }
            g_wgb[i] = s;
        } else if (i < 2*LC){
            int j = i - LC;
            int l = j / CH, d = j % CH;
            const float* base = tw + (size_t)l*CH*CH + d;
            const float* bb = pb + l*CH;
            float s = 0.f;
            for (int c = 0; c < CH; c++) s += base[(size_t)c*CH] * bb[c];
            g_u[j] = s;
        } else if (i < 3*LC){
            int j = i - 2*LC;
            int l = j / CH, d = j % CH;
            const float* base = pw + (size_t)l*CH*CH + d;
            const float* bb = tb + l*CH;
            float s = 0.f;
            for (int c = 0; c < CH; c++) s += base[(size_t)c*CH] * bb[c];
            g_v[j] = s;
        } else if (i < 3*LC + LAYERS){
            int l = i - 3*LC;
            const float* t = tb + l*CH;
            const float* q = pb + l*CH;
            float s = 0.f;
            for (int c = 0; c < CH; c++) s += t[c] * q[c];
            g_cc[l] = s;
        }
    }
}

// ---------------- host ----------------
extern "C" void kernel_launch(void* const* d_in, const int* in_sizes, int n_in,
                              void* d_out, int out_size)
{
    (void)in_sizes; (void)n_in; (void)out_size;
    const float* img     = (const float*)d_in[0];
    const float* trans_w = (const float*)d_in[1];
    const float* trans_b = (const float*)d_in[2];
    const float* gw = (const float*)d_in[3];
    const float* gb = (const float*)d_in[4];
    const float* tw = (const float*)d_in[5];
    const float* tb = (const float*)d_in[6];
    const float* pw = (const float*)d_in[7];
    const float* pb = (const float*)d_in[8];
    const float* ww = (const float*)d_in[9];
    const float* wb = (const float*)d_in[10];
    const float* bn_gamma = (const float*)d_in[11];
    const float* bn_beta  = (const float*)d_in[12];
    const float* bn_mean  = (const float*)d_in[13];
    const float* bn_var   = (const float*)d_in[14];
    float* out = (float*)d_out;

    float* X;
    cudaGetSymbolAddress((void**)&X, g_X);

    cudaFuncSetAttribute(encvm_gemm, cudaFuncAttributeMaxDynamicSharedMemorySize, SMEM_DYN);
    cudaFuncSetAttribute(qkv_gemm,   cudaFuncAttributeMaxDynamicSharedMemorySize, SMEM_DYN);
    cudaFuncSetAttribute(attn_r,     cudaFuncAttributeMaxDynamicSharedMemorySize, SMEM_DYN);
    cudaFuncSetAttribute(attn_y<0>,  cudaFuncAttributeMaxDynamicSharedMemorySize, SMEM_Y);
    cudaFuncSetAttribute(attn_y<1>,  cudaFuncAttributeMaxDynamicSharedMemorySize, SMEM_Y);

    prep_all<<<SPLIT_CTAS + TSP_CTAS + PREP_CTAS, 256>>>(
        img, trans_w, gw, tw, ww, pw, gb, pb, tb);
    encvm_gemm<<<992, 256, SMEM_DYN>>>(trans_b);

    for (int l = 0; l < LAYERS; l++){
        qkv_gemm<<<dim3(QP/128, MTOT/128), 256, SMEM_DYN>>>(l);
        attn_r<<<BATCH, 256, SMEM_DYN>>>(l);
        if (l == LAYERS-1){
            attn_y<1><<<dim3(4, BATCH), 256, SMEM_Y>>>(
                out, l, wb + l*CH,
                bn_gamma + l*CH, bn_beta + l*CH, bn_mean + l*CH, bn_var + l*CH);
        } else {
            attn_y<0><<<dim3(4, BATCH), 256, SMEM_Y>>>(
                X, l, wb + l*CH,
                bn_gamma + l*CH, bn_beta + l*CH, bn_mean + l*CH, bn_var + l*CH);
        }
    }
}